// round 17
// baseline (speedup 1.0000x reference)
#include <cuda_runtime.h>
#include <math.h>

#define BB 32
#define TT 512
#define TT1 513
#define SD 256
#define HD 512
#define BT (BB*TT)
#define MS (BT*SD)
#define MT (BT*TT)
#define NB 32

__device__ __align__(128) float g_tp[MS], g_tc[MS], g_gg[MS];
__device__ __align__(128) float g_A[MT], g_L[MT], g_Li[MT], g_cat[MT], g_cat2[MT];
__device__ __align__(128) float g_P[BB*TT*NB];
__device__ __align__(128) float g_cs[BT], g_ar[BT], g_dg[BT];
__device__ __align__(128) int   g_piv[BT];
__device__ __align__(128) int   g_srcrow[BT];
__device__ __align__(128) int   g_arr[BT];
__device__ __align__(128) int   g_flag[BB];
__device__ __align__(128) int   g_done[BB];

// channel remap into x: 1 = sem half, 2 = struct half (halves are 128-aligned)
template<int MAP> __device__ __forceinline__ int rmap(int c) {
  if (MAP == 1) return c + ((c >= 128) ? 128 : 0);
  if (MAP == 2) return c + 128 + ((c >= 128) ? 128 : 0);
  return c;
}

// root scores (struct read remapped from x); zeroes cs + sync flags
__global__ void root_k(const float* __restrict__ x, const int* __restrict__ seq) {
  int g = blockIdx.x*blockDim.x + threadIdx.x;
  int w = g >> 5, lane = g & 31;
  if (w >= BT) return;
  if (lane == 1) g_cs[w] = 0.0f;
  if (lane == 2 && w < BB) { g_flag[w] = 0; g_done[w] = 0; }
  const float* xp = x + (size_t)w*HD;
  extern __shared__ float swr[];  // unused; keep none
  float acc = 0.f;
  const float* wr = (const float*)0;
  (void)wr;
  // w_root is passed via constant path: reload per call below
  // (handled by caller variant)
  (void)xp; (void)acc; (void)seq;
}

// actual root kernel (w_root as arg)
__global__ void root2_k(const float* __restrict__ x, const float* __restrict__ wrv,
                        const int* __restrict__ seq) {
  int g = blockIdx.x*blockDim.x + threadIdx.x;
  int w = g >> 5, lane = g & 31;
  if (w >= BT) return;
  if (lane == 1) g_cs[w] = 0.0f;
  if (lane == 2 && w < BB) { g_flag[w] = 0; g_done[w] = 0; }
  const float* xp = x + (size_t)w*HD;
  float acc = 0.f;
  for (int c = lane; c < SD; c += 32) acc += xp[rmap<2>(c)] * wrv[c];
  for (int o = 16; o > 0; o >>= 1) acc += __shfl_down_sync(0xffffffffu, acc, o);
  if (lane == 0) {
    int b = w >> 9, t = w & 511;
    g_ar[w] = (t < seq[b]) ? expf(acc) : 0.0f;
  }
}

// ---------------- on-the-fly Laplacian (round 0 of inversion) ----------------
__device__ __forceinline__ float LvalS(int b, int i, int j, int len) {
  if (i == 0) return g_ar[b*TT + j];
  float v = -g_A[(size_t)b*TT*TT + (size_t)i*TT + j];
  if (i == j) v += g_cs[b*TT + j] + ((j >= len) ? 1.0f : 0.0f);
  return v;
}
__device__ __forceinline__ float4 Lval4(int b, int i, int j, int len) {
  if (i == 0) {
    const float* a = g_ar + b*TT + j;
    return make_float4(a[0], a[1], a[2], a[3]);
  }
  float4 v = *(const float4*)(g_A + (size_t)b*TT*TT + (size_t)i*TT + j);
  v.x = -v.x; v.y = -v.y; v.z = -v.z; v.w = -v.w;
  if (i >= j && i < j+4) {
    float d = g_cs[b*TT + i] + ((i >= len) ? 1.0f : 0.0f);
    ((float*)&v)[i-j] += d;
  }
  return v;
}

// ---------------- persistent blocked-GJ inverse ----------------
__global__ __launch_bounds__(1024) void inv_k(float* __restrict__ Lb, float* __restrict__ Lib,
                                              const int* __restrict__ seq) {
  extern __shared__ float sm[];
  float* PsS = sm;
  float* Rs  = sm + TT*33;
  __shared__ float colA[TT], colB[TT];
  __shared__ float rowk[NB];
  __shared__ int cur[TT], logpos[TT];
  __shared__ float sPinv; __shared__ int sPr;
  __shared__ int smap[TT];
  int b = blockIdx.y, x = blockIdx.x, tid = threadIdx.x;
  float* Pg = g_P + (size_t)b*TT*NB;
  int len = seq[b];

  for (int r = 0; r < TT/NB; ++r) {
    int k0 = r*NB;
    const float* src = ((r & 1) ? Lib : Lb) + (size_t)b*TT*TT;
    float*       dst = ((r & 1) ? Lb  : Lib) + (size_t)b*TT*TT;
    __syncthreads();

    if (x == 0) {
      if (tid == 0 && r > 0) {
        while (atomicAdd(&g_done[b], 0) < 4*r) {}
        __threadfence();
      }
      __syncthreads();
      int c = tid >> 5, lane = tid & 31;
      for (int idx = tid; idx < TT*NB; idx += 1024) {
        int i = idx >> 5, cc = idx & 31;
        PsS[i*33+cc] = (r == 0) ? LvalS(b, i, cc, len) : src[(size_t)i*TT + k0 + cc];
      }
      if (tid < TT) { cur[tid] = tid; logpos[tid] = tid; }
      __syncthreads();
      float val[16];
#pragma unroll
      for (int w = 0; w < 16; ++w) val[w] = PsS[(lane+32*w)*33 + c];
      if (c == 0) {
        float bv = -1.f; int bp = lane; float bs = 0.f;
#pragma unroll
        for (int w = 0; w < 16; ++w) {
          int p = lane + 32*w;
          colA[p] = val[w];
          if (p >= k0) {
            float av = fabsf(val[w]);
            if (av > bv) { bv = av; bp = p; bs = val[w]; }
          }
        }
        for (int o = 16; o > 0; o >>= 1) {
          float v2 = __shfl_down_sync(0xffffffffu, bv, o);
          int   p2 = __shfl_down_sync(0xffffffffu, bp, o);
          float s2 = __shfl_down_sync(0xffffffffu, bs, o);
          if (v2 > bv) { bv = v2; bp = p2; bs = s2; }
        }
        if (lane == 0) {
          int lp = logpos[bp];
          int pk = cur[k0];
          cur[k0] = bp; cur[lp] = pk;
          logpos[bp] = k0; logpos[pk] = lp;
          g_piv[b*TT + k0] = lp;
          sPr = bp; sPinv = 1.0f / bs;
        }
      }
      for (int kk = 0; kk < NB; ++kk) {
        __syncthreads();
        int pr = sPr; float pinv = sPinv;
#pragma unroll
        for (int w = 0; w < 16; ++w) {
          if (lane + 32*w == pr) {
            float v = (c == kk) ? 1.0f : val[w];
            v *= pinv;
            val[w] = v;
            rowk[c] = v;
          }
        }
        __syncthreads();
        float rk = rowk[c];
        const float* colR = (kk & 1) ? colB : colA;
#pragma unroll
        for (int w = 0; w < 16; ++w) {
          int p = lane + 32*w;
          if (p != pr) {
            float m = colR[p];
            float cv = (c == kk) ? 0.0f : val[w];
            val[w] = cv - m*rk;
          }
        }
        if (kk < NB-1 && c == kk+1) {
          float* colW = (kk & 1) ? colA : colB;
          int kn = k0 + kk + 1;
          float bv = -1.f; int bp = lane; float bs = 0.f;
#pragma unroll
          for (int w = 0; w < 16; ++w) {
            int p = lane + 32*w;
            colW[p] = val[w];
            if (logpos[p] >= kn) {
              float av = fabsf(val[w]);
              if (av > bv) { bv = av; bp = p; bs = val[w]; }
            }
          }
          for (int o = 16; o > 0; o >>= 1) {
            float v2 = __shfl_down_sync(0xffffffffu, bv, o);
            int   p2 = __shfl_down_sync(0xffffffffu, bp, o);
            float s2 = __shfl_down_sync(0xffffffffu, bs, o);
            if (v2 > bv) { bv = v2; bp = p2; bs = s2; }
          }
          __syncwarp();
          if (lane == 0) {
            int lp = logpos[bp];
            int pk = cur[kn];
            cur[kn] = bp; cur[lp] = pk;
            logpos[bp] = kn; logpos[pk] = lp;
            g_piv[b*TT + kn] = lp;
            sPr = bp; sPinv = 1.0f / bs;
          }
        }
      }
#pragma unroll
      for (int w = 0; w < 16; ++w) {
        int p = lane + 32*w;
        PsS[logpos[p]*33 + c] = val[w];
      }
      if (tid < TT) { g_srcrow[b*TT + tid] = cur[tid]; smap[tid] = cur[tid]; }
      __syncthreads();
      for (int idx = tid; idx < TT*NB; idx += 1024) {
        int i = idx >> 5, cc = idx & 31;
        Pg[i*32+cc] = PsS[i*33+cc];
      }
      __syncthreads();
      if (tid == 0) { __threadfence(); atomicExch(&g_flag[b], r+1); }
    } else {
      if (tid == 0) {
        while (atomicAdd(&g_flag[b], 0) < r+1) {}
        __threadfence();
      }
      __syncthreads();
      if (tid < TT) smap[tid] = g_srcrow[b*TT + tid];
      __syncthreads();
      for (int idx = tid; idx < TT*NB; idx += 1024) {
        int i = idx >> 5, cc = idx & 31;
        PsS[i*33+cc] = Pg[i*32+cc];
      }
    }
    // ---- update slice x ----
    int jbase = x*128;
    for (int idx = tid; idx < NB*128; idx += 1024) {
      int k = idx >> 7, cc = idx & 127;
      int sr = smap[k0+k];
      Rs[k*132+cc] = (r == 0) ? LvalS(b, sr, jbase+cc, len)
                              : src[(size_t)sr*TT + jbase + cc];
    }
    __syncthreads();
    int tx = tid & 31, ty = tid >> 5;
    int j = jbase + tx*4;
    if (j >= k0 && j < k0 + NB) {
      int pc = j - k0;
      for (int rr = 0; rr < 4; ++rr) {
        int i0 = rr*128 + ty*4;
#pragma unroll
        for (int q = 0; q < 4; ++q) {
          int i = i0 + q;
          *(float4*)(dst + (size_t)i*TT + j) = *(const float4*)(Pg + (size_t)i*32 + pc);
        }
      }
    } else {
      for (int rr = 0; rr < 4; ++rr) {
        int i0 = rr*128 + ty*4;
        float acc[4][4] = {};
#pragma unroll 8
        for (int k = 0; k < NB; ++k) {
          float4 rv = *(const float4*)(Rs + k*132 + tx*4);
          float p0 = PsS[(i0+0)*33+k], p1 = PsS[(i0+1)*33+k];
          float p2 = PsS[(i0+2)*33+k], p3 = PsS[(i0+3)*33+k];
          acc[0][0]+=p0*rv.x; acc[0][1]+=p0*rv.y; acc[0][2]+=p0*rv.z; acc[0][3]+=p0*rv.w;
          acc[1][0]+=p1*rv.x; acc[1][1]+=p1*rv.y; acc[1][2]+=p1*rv.z; acc[1][3]+=p1*rv.w;
          acc[2][0]+=p2*rv.x; acc[2][1]+=p2*rv.y; acc[2][2]+=p2*rv.z; acc[2][3]+=p2*rv.w;
          acc[3][0]+=p3*rv.x; acc[3][1]+=p3*rv.y; acc[3][2]+=p3*rv.z; acc[3][3]+=p3*rv.w;
        }
#pragma unroll
        for (int q = 0; q < 4; ++q) {
          int i = i0 + q;
          float4 res;
          if (i >= k0 && i < k0 + NB) res = make_float4(0.f,0.f,0.f,0.f);
          else if (r == 0) res = Lval4(b, smap[i], j, len);
          else res = *(const float4*)(src + (size_t)smap[i]*TT + j);
          res.x += acc[q][0]; res.y += acc[q][1]; res.z += acc[q][2]; res.w += acc[q][3];
          *(float4*)(dst + (size_t)i*TT + j) = res;
        }
      }
    }
    __threadfence();
    __syncthreads();
    if (tid == 0) atomicAdd(&g_done[b], 1);
  }
}

__global__ void perm_k(float* __restrict__ out2) {
  __shared__ int arr[TT];
  int b = blockIdx.x, tid = threadIdx.x;
  if (tid == 0) {
    for (int j = 0; j < TT; ++j) arr[j] = j;
    for (int l = TT-1; l >= 0; --l) {
      int p = g_piv[b*TT + l];
      if (p != l) { int t = arr[l]; arr[l] = arr[p]; arr[p] = t; }
    }
  }
  __syncthreads();
  const float* a = g_L + (size_t)b*TT*TT;
  int j = tid;
  g_arr[b*TT + j] = arr[j];
  g_dg[b*TT + j] = a[(size_t)j*TT + arr[j]];
  out2[(size_t)b*TT1*TT + j] = g_ar[b*TT + j] * a[(size_t)j*TT + arr[0]];
}

__global__ __launch_bounds__(1024) void pij_k(float* __restrict__ out2) {
  __shared__ float Ts[32][33];
  __shared__ int sarr[32];
  int b = blockIdx.z;
  int i0 = blockIdx.y*32, j0 = blockIdx.x*32;
  int tx = threadIdx.x, ty = threadIdx.y;
  const float* Lf = g_L + (size_t)b*TT*TT;
  if (ty == 0) sarr[tx] = g_arr[b*TT + i0 + tx];
  __syncthreads();
  Ts[ty][tx] = Lf[(size_t)(j0+ty)*TT + sarr[tx]];
  __syncthreads();
  int i = i0 + ty, j = j0 + tx;
  float av  = g_A[(size_t)b*TT*TT + (size_t)i*TT + j];
  float dj  = (j > 0) ? g_dg[b*TT + j] : 0.0f;
  float lji = (i > 0) ? Ts[tx][ty] : 0.0f;
  out2[(size_t)b*TT1*TT + (size_t)(i+1)*TT + j] = av * (dj - lji);
}

// ---------------- tf32 tensor-core GEMM (double-buffered; AMAP/BMAP channel remap) ----------------
#define TFA 136
#define TFB 72
__device__ __forceinline__ float f2tf(float f) {
  unsigned u; asm("cvt.rna.tf32.f32 %0, %1;" : "=r"(u) : "f"(f));
  return __uint_as_float(u);
}
__device__ __forceinline__ void mma_tf32(float* d, const unsigned* a, unsigned b0, unsigned b1) {
  asm volatile("mma.sync.aligned.m16n8k8.row.col.f32.tf32.tf32.f32 "
    "{%0,%1,%2,%3}, {%4,%5,%6,%7}, {%8,%9}, {%0,%1,%2,%3};"
    : "+f"(d[0]), "+f"(d[1]), "+f"(d[2]), "+f"(d[3])
    : "r"(a[0]), "r"(a[1]), "r"(a[2]), "r"(a[3]), "r"(b0), "r"(b1));
}
template<int MODE, bool SPLIT, int AMAP, int BMAP>
__global__ __launch_bounds__(256)
void tgemm_k(const float* __restrict__ A, int lda, long long sA,
             const float* __restrict__ B, int ldb, long long sB,
             float* __restrict__ C, int ldc, long long sC,
             int K, const float* __restrict__ bias, int act, const int* __restrict__ seq,
             const float* __restrict__ aux)
{
  __shared__ __align__(16) float As[2][16*TFA];
  __shared__ __align__(16) float Bs[2][16*TFB];
  __shared__ float scol[64];
  int tid = threadIdx.x;
  int m0 = blockIdx.y*128, n0 = blockIdx.x*64;
  const float* Ab = A + (size_t)blockIdx.z*sA;
  const float* Bb = B + (size_t)blockIdx.z*sB;
  float* Cb = C + (size_t)blockIdx.z*sC;
  int warp = tid>>5, lane = tid&31;
  int wm = (warp&3)*32, wn = (warp>>2)*32;
  int g = lane>>2, la3 = lane&3;
  float acc[2][4][4];
#pragma unroll
  for(int a=0;a<2;a++)
#pragma unroll
    for(int b=0;b<4;b++)
#pragma unroll
      for(int c=0;c<4;c++) acc[a][b][c]=0.f;

  const int NT = K >> 4;
  float4 va0, va1, vb;

#define TG_LOAD(k0) do { \
    if (MODE == 2) { \
      int kr0 = tid >> 5, c40 = (tid & 31)*4; \
      va0 = *(const float4*)(Ab + (size_t)((k0)+kr0)*lda + m0 + c40); \
      int i1 = tid + 256; int kr1 = i1 >> 5, c41 = (i1 & 31)*4; \
      va1 = *(const float4*)(Ab + (size_t)((k0)+kr1)*lda + m0 + c41); \
    } else { \
      int r0 = tid >> 2, c40 = rmap<AMAP>((k0) + (tid & 3)*4); \
      va0 = *(const float4*)(Ab + (size_t)(m0+r0)*lda + c40); \
      int i1 = tid + 256; int r1 = i1 >> 2, c41 = rmap<AMAP>((k0) + (i1 & 3)*4); \
      va1 = *(const float4*)(Ab + (size_t)(m0+r1)*lda + c41); \
    } \
    if (MODE == 0) { \
      int r = tid >> 2, c4 = (tid & 3)*4; \
      vb = *(const float4*)(Bb + (size_t)(n0+r)*ldb + (k0) + c4); \
    } else { \
      int kr = tid >> 4, c4 = rmap<BMAP>(n0 + (tid & 15)*4); \
      vb = *(const float4*)(Bb + (size_t)((k0)+kr)*ldb + c4); \
    } \
  } while (0)

#define TG_STORE(s) do { \
    float4 w0 = va0, w1 = va1, wb = vb; \
    if (!SPLIT) { \
      w0.x = f2tf(w0.x); w0.y = f2tf(w0.y); w0.z = f2tf(w0.z); w0.w = f2tf(w0.w); \
      w1.x = f2tf(w1.x); w1.y = f2tf(w1.y); w1.z = f2tf(w1.z); w1.w = f2tf(w1.w); \
      wb.x = f2tf(wb.x); wb.y = f2tf(wb.y); wb.z = f2tf(wb.z); wb.w = f2tf(wb.w); \
    } \
    if (MODE == 2) { \
      int kr0 = tid >> 5, c40 = (tid & 31)*4; \
      *(float4*)(As[s] + kr0*TFA + c40) = w0; \
      int i1 = tid + 256; int kr1 = i1 >> 5, c41 = (i1 & 31)*4; \
      *(float4*)(As[s] + kr1*TFA + c41) = w1; \
    } else { \
      int r0 = tid >> 2, c40 = (tid & 3)*4; \
      As[s][(c40+0)*TFA + r0] = w0.x; As[s][(c40+1)*TFA + r0] = w0.y; \
      As[s][(c40+2)*TFA + r0] = w0.z; As[s][(c40+3)*TFA + r0] = w0.w; \
      int i1 = tid + 256; int r1 = i1 >> 2, c41 = (i1 & 3)*4; \
      As[s][(c41+0)*TFA + r1] = w1.x; As[s][(c41+1)*TFA + r1] = w1.y; \
      As[s][(c41+2)*TFA + r1] = w1.z; As[s][(c41+3)*TFA + r1] = w1.w; \
    } \
    if (MODE == 0) { \
      int r = tid >> 2, c4 = (tid & 3)*4; \
      Bs[s][(c4+0)*TFB + r] = wb.x; Bs[s][(c4+1)*TFB + r] = wb.y; \
      Bs[s][(c4+2)*TFB + r] = wb.z; Bs[s][(c4+3)*TFB + r] = wb.w; \
    } else { \
      int kr = tid >> 4, c4 = (tid & 15)*4; \
      *(float4*)(Bs[s] + kr*TFB + c4) = wb; \
    } \
  } while (0)

  if (tid < 64) scol[tid] = 0.0f;
  TG_LOAD(0);
  TG_STORE(0);
  __syncthreads();

  for (int t = 0; t < NT; ++t) {
    int cb = t & 1;
    if (t+1 < NT) TG_LOAD((t+1)*16);
#pragma unroll
    for (int ks = 0; ks < 2; ++ks) {
      int kb = ks*8;
      unsigned ah[2][4], al[2][4];
#pragma unroll
      for (int mt = 0; mt < 2; ++mt) {
        const float* ap = As[cb] + (kb + la3)*TFA + wm + mt*16 + g;
        float f0 = ap[0], f1 = ap[8], f2 = ap[4*TFA], f3 = ap[4*TFA + 8];
        if (SPLIT) {
          float h0 = f2tf(f0), h1 = f2tf(f1), h2 = f2tf(f2), h3 = f2tf(f3);
          ah[mt][0] = __float_as_uint(h0); al[mt][0] = __float_as_uint(f2tf(f0 - h0));
          ah[mt][1] = __float_as_uint(h1); al[mt][1] = __float_as_uint(f2tf(f1 - h1));
          ah[mt][2] = __float_as_uint(h2); al[mt][2] = __float_as_uint(f2tf(f2 - h2));
          ah[mt][3] = __float_as_uint(h3); al[mt][3] = __float_as_uint(f2tf(f3 - h3));
        } else {
          ah[mt][0] = __float_as_uint(f0); ah[mt][1] = __float_as_uint(f1);
          ah[mt][2] = __float_as_uint(f2); ah[mt][3] = __float_as_uint(f3);
        }
      }
#pragma unroll
      for (int nt = 0; nt < 4; ++nt) {
        const float* bp = Bs[cb] + (kb + la3)*TFB + wn + nt*8 + g;
        float bf0 = bp[0], bf1 = bp[4*TFB];
        unsigned bh0, bh1, bl0, bl1;
        if (SPLIT) {
          float h0 = f2tf(bf0), h1 = f2tf(bf1);
          bh0 = __float_as_uint(h0); bl0 = __float_as_uint(f2tf(bf0 - h0));
          bh1 = __float_as_uint(h1); bl1 = __float_as_uint(f2tf(bf1 - h1));
        } else {
          bh0 = __float_as_uint(bf0); bh1 = __float_as_uint(bf1);
          bl0 = bl1 = 0;
        }
#pragma unroll
        for (int mt = 0; mt < 2; ++mt) {
          mma_tf32(acc[mt][nt], ah[mt], bh0, bh1);
          if (SPLIT) {
            mma_tf32(acc[mt][nt], ah[mt], bl0, bl1);
            mma_tf32(acc[mt][nt], al[mt], bh0, bh1);
          }
        }
      }
    }
    if (t+1 < NT) TG_STORE(cb ^ 1);
    __syncthreads();
  }

  int len = (act == 3) ? seq[blockIdx.z] : 0;
#pragma unroll
  for (int mt = 0; mt < 2; ++mt) {
    int mrow = m0 + wm + mt*16 + g;
#pragma unroll
    for (int nt = 0; nt < 4; ++nt) {
      int ncol = n0 + wn + nt*8 + la3*2;
      float b0v = 0.f, b1v = 0.f;
      if (bias && act != 4) { b0v = bias[ncol]; b1v = bias[ncol+1]; }
      float v[4] = { acc[mt][nt][0] + b0v, acc[mt][nt][1] + b1v,
                     acc[mt][nt][2] + b0v, acc[mt][nt][3] + b1v };
      if (act == 1) {
        v[0]=tanhf(v[0]); v[1]=tanhf(v[1]); v[2]=tanhf(v[2]); v[3]=tanhf(v[3]);
      } else if (act == 2) {
#pragma unroll
        for (int q = 0; q < 4; ++q) v[q] = v[q]>=0.f ? v[q] : 0.01f*v[q];
      } else if (act == 3) {
#pragma unroll
        for (int q = 0; q < 4; ++q) {
          int gi = mrow + (q >= 2 ? 8 : 0);
          int gj = ncol + (q & 1);
          v[q] = (gi != gj && gi < len && gj < len) ? expf(v[q]) : 0.0f;
        }
        atomicAdd(&scol[ncol   - n0], v[0] + v[2]);
        atomicAdd(&scol[ncol+1 - n0], v[1] + v[3]);
      } else if (act == 4) {
        float pr0 = aux[(size_t)blockIdx.z*TT1*TT + mrow];
        float pr8 = aux[(size_t)blockIdx.z*TT1*TT + mrow + 8];
        v[0] += pr0*bias[ncol]; v[1] += pr0*bias[ncol+1];
        v[2] += pr8*bias[ncol]; v[3] += pr8*bias[ncol+1];
      }
      *(float2*)(Cb + (size_t)mrow*ldc + ncol) = make_float2(v[0], v[1]);
      *(float2*)(Cb + (size_t)(mrow+8)*ldc + ncol) = make_float2(v[2], v[3]);
    }
  }
  if (act == 3) {
    __syncthreads();
    if (tid < 64) atomicAdd(&g_cs[blockIdx.z*TT + n0 + tid], scol[tid]);
  }
#undef TG_LOAD
#undef TG_STORE
}

// ---------------- launch ----------------
extern "C" void kernel_launch(void* const* d_in, const int* in_sizes, int n_in,
                              void* d_out, int out_size) {
  (void)in_sizes; (void)n_in; (void)out_size;
  const float* x     = (const float*)d_in[0];
  const int*   seq   = (const int*)  d_in[1];
  const float* W_tp  = (const float*)d_in[2];
  const float* b_tp  = (const float*)d_in[3];
  const float* W_tc  = (const float*)d_in[4];
  const float* b_tc  = (const float*)d_in[5];
  const float* W_fij = (const float*)d_in[6];
  const float* w_root= (const float*)d_in[7];
  const float* r_emb = (const float*)d_in[8];
  const float* W_r   = (const float*)d_in[9];
  const float* b_r   = (const float*)d_in[10];
  const float* W_pc  = (const float*)d_in[11];
  const float* b_pc  = (const float*)d_in[12];
  float* out1 = (float*)d_out;
  float* out2 = out1 + (size_t)BT*SD;

  float *tp,*tc,*gg,*A,*L,*Li,*cat,*cat2;
  cudaGetSymbolAddress((void**)&tp,   g_tp);
  cudaGetSymbolAddress((void**)&tc,   g_tc);
  cudaGetSymbolAddress((void**)&gg,   g_gg);
  cudaGetSymbolAddress((void**)&A,    g_A);
  cudaGetSymbolAddress((void**)&L,    g_L);
  cudaGetSymbolAddress((void**)&Li,   g_Li);
  cudaGetSymbolAddress((void**)&cat,  g_cat);
  cudaGetSymbolAddress((void**)&cat2, g_cat2);

  const int INV_SMEM = TT*33*4 + NB*132*4;   // 84480
  cudaFuncSetAttribute(inv_k, cudaFuncAttributeMaxDynamicSharedMemorySize, INV_SMEM);

  const long long sTT = (long long)TT*TT, sTS = (long long)TT*SD,
                  sTH = (long long)TT*HD, sP = (long long)TT1*TT;
  const long long sX = (long long)TT*HD;
  const float* pij = out2 + TT;

  root2_k<<<BT*32/256, 256>>>(x, w_root, seq);   // also zeroes cs + flags
  tgemm_k<0,true,2,0><<<dim3(4,128,1),256>>>(x, HD, 0, W_tp, SD, 0, tp, SD, 0, SD, b_tp, 1, 0, 0);
  tgemm_k<0,true,2,0><<<dim3(4,128,1),256>>>(x, HD, 0, W_tc, SD, 0, tc, SD, 0, SD, b_tc, 1, 0, 0);
  tgemm_k<1,true,0,0><<<dim3(4,128,1),256>>>(tp, SD, 0, W_fij, SD, 0, gg, SD, 0, SD, 0, 0, 0, 0);
  tgemm_k<0,true,0,0><<<dim3(8,4,BB),256>>>(gg, SD, sTS, tc, SD, sTS, A, TT, sTT, SD, 0, 3, seq, 0);
  inv_k<<<dim3(4, BB), 1024, INV_SMEM>>>(L, Li, seq);
  perm_k<<<BB, TT>>>(out2);
  pij_k<<<dim3(16,16,BB), dim3(32,32)>>>(out2);
  tgemm_k<2,false,0,1><<<dim3(4,4,BB),256>>>(pij, TT, sP, x, HD, sX, cat, HD, sTH, TT, r_emb, 4, 0, out2);
  tgemm_k<1,false,0,1><<<dim3(4,4,BB),256>>>(pij, TT, sP, x, HD, sX, cat + SD, HD, sTH, TT, 0, 0, 0, 0);
  tgemm_k<0,false,0,0><<<dim3(4,128,1),256>>>(cat, HD, 0, W_r, HD, 0, cat2, HD, 0, HD, b_r, 2, 0, 0);
  tgemm_k<1,false,0,0><<<dim3(4,4,BB),256>>>(pij, TT, sP, cat2, HD, sTH, cat2 + SD, HD, sTH, TT, 0, 0, 0, 0);
  tgemm_k<0,false,0,0><<<dim3(4,128,1),256>>>(cat2, HD, 0, W_pc, HD, 0, out1, SD, 0, HD, b_pc, 2, 0, 0);
}